// round 14
// baseline (speedup 1.0000x reference)
#include <cuda_runtime.h>
#include <cuda_fp16.h>
#include <cstdint>

// Problem constants
#define BATCH   8
#define NPTS    200000
#define NCH     32
#define RES     128
#define RR      (RES * RES)       // 16384
#define NPLANES 3
#define NBP     (BATCH * NPLANES) // 24
#define TOTPTS  (BATCH * NPTS)    // 1.6M

// Scratch (static __device__, allocation-free).
// g_featS: features materialized in SORTED bin order, fp16, 64B per
// (point,plane): [bp][pos][c]. 307 MB.
__device__ __align__(128) __half g_featS[(size_t)NBP * NPTS * NCH];
__device__ __align__(128) int    g_cnt[NBP * RR];     // zero at load; re-zeroed by gather
__device__ __align__(128) int    g_offs[NBP * RR];
__device__ __align__(128) int    g_cursor[NBP * RR];

// Bin math — mirrors reference exactly.
__device__ __forceinline__ int bin_of(float v) {
    const float DEN  = 1.0f + 1e-5f;
    const float CLMP = 1.0f - 1e-5f;
    float u = ((v + 1.0f) * 0.5f - 0.5f) / DEN + 0.5f;
    u = fminf(fmaxf(u, 0.0f), CLMP);
    return (int)(u * (float)RES);
}

__device__ __forceinline__ void bins3(const float* __restrict__ xyz, int gid,
                                      int& lin0, int& lin1, int& lin2) {
    const float* p = xyz + (size_t)gid * 3;
    const int ix = bin_of(p[0]);
    const int iy = bin_of(p[1]);
    const int iz = bin_of(p[2]);
    lin0 = ix + RES * iy;   // xy
    lin1 = iy + RES * iz;   // yz
    lin2 = ix + RES * iz;   // xz
}

// ---------------------------------------------------------------------------
// K1: histogram only. 19 MB xyz read + 4.8M spread int atomics.
// ---------------------------------------------------------------------------
__global__ void __launch_bounds__(256) hist_kernel(const float* __restrict__ xyz) {
    const int gid = blockIdx.x * 256 + threadIdx.x;
    if (gid >= TOTPTS) return;
    const int b = gid / NPTS;
    int lin0, lin1, lin2;
    bins3(xyz, gid, lin0, lin1, lin2);
    const int bp = b * NPLANES;
    atomicAdd(&g_cnt[(bp + 0) * RR + lin0], 1);
    atomicAdd(&g_cnt[(bp + 1) * RR + lin1], 1);
    atomicAdd(&g_cnt[(bp + 2) * RR + lin2], 1);
}

// ---------------------------------------------------------------------------
// K2: exclusive scan of counts within each (b,plane). 24 blocks x 1024 threads.
// ---------------------------------------------------------------------------
__global__ void __launch_bounds__(1024) scan_kernel() {
    __shared__ int ssum[1024];
    const int bp = blockIdx.x;
    const int t  = threadIdx.x;
    const int base = bp * RR + t * 16;

    int local[16];
    int s = 0;
#pragma unroll
    for (int i = 0; i < 16; i++) { local[i] = g_cnt[base + i]; s += local[i]; }
    ssum[t] = s;
    __syncthreads();

    for (int off = 1; off < 1024; off <<= 1) {
        int v = (t >= off) ? ssum[t - off] : 0;
        __syncthreads();
        ssum[t] += v;
        __syncthreads();
    }

    int run = (t > 0) ? ssum[t - 1] : 0;
#pragma unroll
    for (int i = 0; i < 16; i++) {
        g_offs[base + i]   = run;
        g_cursor[base + i] = run;
        run += local[i];
    }
}

// ---------------------------------------------------------------------------
// K3: transpose + fp16-convert + scatter features into SORTED order.
// Block = 256 (32,8) handles 32 points of one batch:
//   phase 1: smem-transpose 32x32 fp32 tile (coalesced feat reads),
//   phase 2: convert once to fp16 tile [point][channel],
//   phase 3: 96 writer threads (point 0..31 x plane 0..2) claim a slot via
//            cursor atomicAdd and write the point's 64B with 4x STG.128.
// Scattered destinations, but each write is 64B contiguous (2 sectors) and
// per-batch regions (38.4 MB) are L2-friendly.
// ---------------------------------------------------------------------------
__global__ void __launch_bounds__(256) transpose_scatter_kernel(const float* __restrict__ xyz,
                                                                const float* __restrict__ feat) {
    __shared__ float  tile[32][33];
    __shared__ __half htile[32][NCH];      // [point][channel], rows 64B
    const int b  = blockIdx.y;
    const int n0 = blockIdx.x * 32;
    const int tx = threadIdx.x, ty = threadIdx.y;
    const int tid = ty * 32 + tx;

#pragma unroll
    for (int i = 0; i < 4; i++) {
        const int c = ty + i * 8;
        tile[c][tx] = feat[((size_t)b * NCH + c) * NPTS + n0 + tx];   // coalesced in n
    }
    __syncthreads();

    // fp16 convert: tid -> (p, c); read tile[c][p] (stride 33, conflict-free)
#pragma unroll
    for (int i = 0; i < 4; i++) {
        const int j = tid + i * 256;
        const int p = j >> 5, c = j & 31;
        htile[p][c] = __float2half(tile[c][p]);
    }
    __syncthreads();

    // Writers: tid < 96: point = tid & 31, plane = tid >> 5
    if (tid < 96) {
        const int point = tid & 31;
        const int plane = tid >> 5;
        const int gid   = b * NPTS + n0 + point;

        int lin[3];
        bins3(xyz, gid, lin[0], lin[1], lin[2]);
        const int bp  = b * NPLANES + plane;
        const int pos = atomicAdd(&g_cursor[bp * RR + lin[plane]], 1);

        const uint4* src = reinterpret_cast<const uint4*>(&htile[point][0]);
        uint4* dst = reinterpret_cast<uint4*>(g_featS + ((size_t)bp * NPTS + pos) * NCH);
        dst[0] = src[0];
        dst[1] = src[1];
        dst[2] = src[2];
        dst[3] = src[3];
    }
}

// ---------------------------------------------------------------------------
// K4: streaming segmented reduce — bins' points are CONTIGUOUS in g_featS.
// Warp per bin x4 (lane = p*8+cq: point slot p 0..3, channel quad cq 0..7).
// All feature loads are independent sequential uint2s; no index indirection.
// Batch-major block order keeps the per-batch region L2-resident.
// ---------------------------------------------------------------------------
__global__ void __launch_bounds__(256) gather_kernel(float* __restrict__ out) {
    __shared__ float s[32][33];

    const int tiles_per_bp = RR / 32;                    // 512
    const int blk  = blockIdx.x;
    const int b    = blk / (NPLANES * tiles_per_bp);     // batch-major
    const int r    = blk - b * (NPLANES * tiles_per_bp);
    const int tile = r / NPLANES;
    const int pl   = r - tile * NPLANES;
    const int bp   = b * NPLANES + pl;
    const int bin0 = tile * 32;

    const int w    = threadIdx.x >> 5;                   // warp 0..7
    const int lane = threadIdx.x & 31;
    const int p    = lane >> 3;                          // point slot 0..3
    const int cq   = lane & 7;                           // channel quad 0..7

    const uint2* ftv = reinterpret_cast<const uint2*>(g_featS + (size_t)bp * NPTS * NCH);

    // Prefetch all 4 bins' metadata up front (independent loads).
    int starts[4], ks[4];
#pragma unroll
    for (int j = 0; j < 4; j++) {
        const int bin = bin0 + j * 8 + w;
        starts[j] = g_offs[bp * RR + bin];
        ks[j]     = g_cnt[bp * RR + bin];
    }

#pragma unroll
    for (int j = 0; j < 4; j++) {
        const int binLocal = j * 8 + w;
        const int start = starts[j];
        const int k     = ks[j];

        float4 acc = {0.f, 0.f, 0.f, 0.f};
#pragma unroll 2
        for (int i = 0; i < k; i += 4) {
            const int slot = i + p;
            if (slot < k) {
                const uint2 v = ftv[(size_t)(start + slot) * 8 + cq];
                const float2 f0 = __half22float2(*reinterpret_cast<const __half2*>(&v.x));
                const float2 f1 = __half22float2(*reinterpret_cast<const __half2*>(&v.y));
                acc.x += f0.x; acc.y += f0.y; acc.z += f1.x; acc.w += f1.y;
            }
        }

        // reduce across point slots p (lanes cq, cq+8, cq+16, cq+24)
#pragma unroll
        for (int off = 8; off <= 16; off <<= 1) {
            acc.x += __shfl_xor_sync(0xffffffffu, acc.x, off);
            acc.y += __shfl_xor_sync(0xffffffffu, acc.y, off);
            acc.z += __shfl_xor_sync(0xffffffffu, acc.z, off);
            acc.w += __shfl_xor_sync(0xffffffffu, acc.w, off);
        }

        if (p == 0) {
            const float inv = 1.0f / (float)max(k, 1);
            s[binLocal][cq * 4 + 0] = acc.x * inv;
            s[binLocal][cq * 4 + 1] = acc.y * inv;
            s[binLocal][cq * 4 + 2] = acc.z * inv;
            s[binLocal][cq * 4 + 3] = acc.w * inv;
        }
        if (lane == 0) g_cnt[bp * RR + bin0 + binLocal] = 0;   // restore zero-invariant
    }
    __syncthreads();

    // Coalesced output write: out[(bp*C + c)*RR + bin0 + i]
    float* ob = out + (size_t)bp * NCH * RR + bin0;
    for (int jj = threadIdx.x; jj < 32 * NCH; jj += 256) {
        const int c = jj >> 5;       // channel
        const int i = jj & 31;       // bin within tile
        ob[(size_t)c * RR + i] = s[i][c];
    }
}

// ---------------------------------------------------------------------------
extern "C" void kernel_launch(void* const* d_in, const int* in_sizes, int n_in,
                              void* d_out, int out_size) {
    const float* xyz  = (const float*)d_in[0];  // (B, N, 3)
    const float* feat = (const float*)d_in[1];  // (B, C, N)
    float* out = (float*)d_out;                 // (B, 3, C, R, R)

    hist_kernel<<<(TOTPTS + 255) / 256, 256>>>(xyz);

    scan_kernel<<<NBP, 1024>>>();

    dim3 g3(NPTS / 32, BATCH), b3(32, 8);
    transpose_scatter_kernel<<<g3, b3>>>(xyz, feat);

    gather_kernel<<<NBP * (RR / 32), 256>>>(out);
}

// round 16
// speedup vs baseline: 1.0641x; 1.0641x over previous
#include <cuda_runtime.h>
#include <cuda_fp16.h>
#include <cstdint>

// Problem constants
#define BATCH   8
#define NPTS    200000
#define NCH     32
#define RES     128
#define RR      (RES * RES)       // 16384
#define NPLANES 3
#define NBP     (BATCH * NPLANES) // 24
#define TOTPTS  (BATCH * NPTS)    // 1.6M

// Scratch (static __device__, allocation-free).
__device__ __align__(128) __half   g_featT[(size_t)BATCH * NPTS * NCH]; // 102 MB point-major fp16
__device__ __align__(128) int      g_cnt[NBP * RR];   // zero at load; re-zeroed by gather
__device__ __align__(128) int      g_offs[NBP * RR];
__device__ __align__(128) uint32_t g_bins[TOTPTS];    // ix | iy<<7 | iz<<14
__device__ __align__(128) uint32_t g_ranks[TOTPTS];   // r0 | r1<<10 | r2<<20
__device__ __align__(128) int      g_order[(size_t)NBP * NPTS];  // sorted point ids

// Bin math — mirrors reference exactly.
__device__ __forceinline__ int bin_of(float v) {
    const float DEN  = 1.0f + 1e-5f;
    const float CLMP = 1.0f - 1e-5f;
    float u = ((v + 1.0f) * 0.5f - 0.5f) / DEN + 0.5f;
    u = fminf(fmaxf(u, 0.0f), CLMP);
    return (int)(u * (float)RES);
}

// ---------------------------------------------------------------------------
// K1: transpose feat (B,C,N) fp32 -> featT (B,N,C) fp16, fused with histogram.
// Histogram atomics RETURN the within-bin rank; pack bins+ranks per point so
// K3 needs no atomics and no xyz re-read.
// ---------------------------------------------------------------------------
__global__ void __launch_bounds__(256) transpose_hist_kernel(const float* __restrict__ xyz,
                                                             const float* __restrict__ feat) {
    __shared__ float tile[32][33];
    const int b  = blockIdx.y;
    const int n0 = blockIdx.x * 32;
    const int tx = threadIdx.x, ty = threadIdx.y;

#pragma unroll
    for (int i = 0; i < 4; i++) {
        const int c = ty + i * 8;
        tile[c][tx] = feat[((size_t)b * NCH + c) * NPTS + n0 + tx];   // coalesced in n
    }
    __syncthreads();
#pragma unroll
    for (int i = 0; i < 4; i++) {
        const int row = ty + i * 8;
        g_featT[((size_t)b * NPTS + n0 + row) * NCH + tx] =
            __float2half(tile[tx][row]);                              // coalesced in c
    }

    // Fused histogram + rank capture: flat thread id covers all points once.
    const int t = (blockIdx.y * gridDim.x + blockIdx.x) * 256 + ty * 32 + tx;
    if (t < TOTPTS) {
        const int pb = t / NPTS;
        const float* p = xyz + (size_t)t * 3;
        const int ix = bin_of(p[0]);
        const int iy = bin_of(p[1]);
        const int iz = bin_of(p[2]);
        const int lin0 = ix + RES * iy;   // xy
        const int lin1 = iy + RES * iz;   // yz
        const int lin2 = ix + RES * iz;   // xz
        const int bp = pb * NPLANES;
        const uint32_t r0 = (uint32_t)atomicAdd(&g_cnt[(bp + 0) * RR + lin0], 1);
        const uint32_t r1 = (uint32_t)atomicAdd(&g_cnt[(bp + 1) * RR + lin1], 1);
        const uint32_t r2 = (uint32_t)atomicAdd(&g_cnt[(bp + 2) * RR + lin2], 1);
        g_bins[t]  = (uint32_t)ix | ((uint32_t)iy << 7) | ((uint32_t)iz << 14);
        g_ranks[t] = r0 | (r1 << 10) | (r2 << 20);
    }
}

// ---------------------------------------------------------------------------
// K2: exclusive scan of counts within each (b,plane). 24 blocks x 1024 threads.
// ---------------------------------------------------------------------------
__global__ void __launch_bounds__(1024) scan_kernel() {
    __shared__ int ssum[1024];
    const int bp = blockIdx.x;
    const int t  = threadIdx.x;
    const int base = bp * RR + t * 16;

    int local[16];
    int s = 0;
#pragma unroll
    for (int i = 0; i < 16; i++) { local[i] = g_cnt[base + i]; s += local[i]; }
    ssum[t] = s;
    __syncthreads();

    for (int off = 1; off < 1024; off <<= 1) {
        int v = (t >= off) ? ssum[t - off] : 0;
        __syncthreads();
        ssum[t] += v;
        __syncthreads();
    }

    int run = (t > 0) ? ssum[t - 1] : 0;
#pragma unroll
    for (int i = 0; i < 16; i++) {
        g_offs[base + i] = run;
        run += local[i];
    }
}

// ---------------------------------------------------------------------------
// K3: ATOMIC-FREE scatter of point ids: pos = offs[bin] + captured rank.
// Sequential reads of g_bins/g_ranks; offs reads are L2-resident (1.5 MB).
// ---------------------------------------------------------------------------
__global__ void __launch_bounds__(256) scatter_idx_kernel() {
    const int gid = blockIdx.x * 256 + threadIdx.x;
    if (gid >= TOTPTS) return;
    const int b = gid / NPTS;
    const int n = gid - b * NPTS;

    const uint32_t pb = g_bins[gid];
    const uint32_t pr = g_ranks[gid];
    const int ix = pb & 127, iy = (pb >> 7) & 127, iz = (pb >> 14) & 127;

    const int lin[3] = { ix + RES * iy, iy + RES * iz, ix + RES * iz };
    const int rk[3]  = { (int)(pr & 1023), (int)((pr >> 10) & 1023), (int)((pr >> 20) & 1023) };

    const int bp = b * NPLANES;
#pragma unroll
    for (int pl = 0; pl < NPLANES; pl++) {
        const int pos = g_offs[(bp + pl) * RR + lin[pl]] + rk[pl];
        g_order[(size_t)(bp + pl) * NPTS + pos] = n;
    }
}

// ---------------------------------------------------------------------------
// K4: atomic-free segmented reduce, index-first, uint4 loads.
// Warp per bin x4. Lane = p*4+cq: point slot p (0..7), channel quad cq (0..3,
// 16B fp16 = 8 channels). One 16B load per point-slot; 8 independent loads in
// flight per warp per bin. fp32 accumulation; cross-p shfl-xor reduce.
// Batch-major block order keeps featT (12.8 MB/batch) L2-resident.
// ---------------------------------------------------------------------------
__global__ void __launch_bounds__(256) gather_kernel(float* __restrict__ out) {
    __shared__ float s[32][33];

    const int tiles_per_bp = RR / 32;                    // 512
    const int blk  = blockIdx.x;
    const int b    = blk / (NPLANES * tiles_per_bp);     // batch-major
    const int r    = blk - b * (NPLANES * tiles_per_bp);
    const int tile = r / NPLANES;
    const int pl   = r - tile * NPLANES;
    const int bp   = b * NPLANES + pl;
    const int bin0 = tile * 32;

    const int w    = threadIdx.x >> 5;                   // warp 0..7
    const int lane = threadIdx.x & 31;
    const int p    = lane >> 2;                          // point slot 0..7
    const int cq   = lane & 3;                           // channel quad 0..3 (8 ch)

    const int*   order = g_order + (size_t)bp * NPTS;
    const uint4* ftv   = reinterpret_cast<const uint4*>(g_featT + (size_t)b * NPTS * NCH);

    // Prefetch all 4 bins' metadata + first index chunks (independent loads).
    int starts[4], ks[4];
#pragma unroll
    for (int j = 0; j < 4; j++) {
        const int bin = bin0 + j * 8 + w;
        starts[j] = g_offs[bp * RR + bin];
        ks[j]     = g_cnt[bp * RR + bin];
    }
    int idx0[4];
#pragma unroll
    for (int j = 0; j < 4; j++) {
        const int m = min(ks[j], 32);
        idx0[j] = (lane < m) ? order[starts[j] + lane] : 0;
    }

#pragma unroll
    for (int j = 0; j < 4; j++) {
        const int binLocal = j * 8 + w;
        const int k = ks[j];

        float acc[8] = {0.f, 0.f, 0.f, 0.f, 0.f, 0.f, 0.f, 0.f};

        const int m0 = min(k, 32);
        for (int i = 0; i < m0; i += 8) {
            const int slot = i + p;
            const int n = __shfl_sync(0xffffffffu, idx0[j], slot & 31);
            if (slot < m0) {
                const uint4 v = ftv[(size_t)n * 4 + cq];
                const float2 f0 = __half22float2(*reinterpret_cast<const __half2*>(&v.x));
                const float2 f1 = __half22float2(*reinterpret_cast<const __half2*>(&v.y));
                const float2 f2 = __half22float2(*reinterpret_cast<const __half2*>(&v.z));
                const float2 f3 = __half22float2(*reinterpret_cast<const __half2*>(&v.w));
                acc[0] += f0.x; acc[1] += f0.y; acc[2] += f1.x; acc[3] += f1.y;
                acc[4] += f2.x; acc[5] += f2.y; acc[6] += f3.x; acc[7] += f3.y;
            }
        }
        // Rare spill: bins with k > 32.
        for (int base = 32; base < k; base += 32) {
            const int m = min(32, k - base);
            int idxv = 0;
            if (lane < m) idxv = order[starts[j] + base + lane];
            for (int i = 0; i < m; i += 8) {
                const int slot = i + p;
                const int n = __shfl_sync(0xffffffffu, idxv, slot & 31);
                if (slot < m) {
                    const uint4 v = ftv[(size_t)n * 4 + cq];
                    const float2 f0 = __half22float2(*reinterpret_cast<const __half2*>(&v.x));
                    const float2 f1 = __half22float2(*reinterpret_cast<const __half2*>(&v.y));
                    const float2 f2 = __half22float2(*reinterpret_cast<const __half2*>(&v.z));
                    const float2 f3 = __half22float2(*reinterpret_cast<const __half2*>(&v.w));
                    acc[0] += f0.x; acc[1] += f0.y; acc[2] += f1.x; acc[3] += f1.y;
                    acc[4] += f2.x; acc[5] += f2.y; acc[6] += f3.x; acc[7] += f3.y;
                }
            }
        }

        // reduce across the 8 point slots (xor 4, 8, 16 over lanes)
#pragma unroll
        for (int off = 4; off <= 16; off <<= 1) {
#pragma unroll
            for (int t2 = 0; t2 < 8; t2++)
                acc[t2] += __shfl_xor_sync(0xffffffffu, acc[t2], off);
        }

        if (p == 0) {
            const float inv = 1.0f / (float)max(k, 1);
#pragma unroll
            for (int t2 = 0; t2 < 8; t2++)
                s[binLocal][cq * 8 + t2] = acc[t2] * inv;
        }
        if (lane == 0) g_cnt[bp * RR + bin0 + binLocal] = 0;   // restore zero-invariant
    }
    __syncthreads();

    // Coalesced output write: out[(bp*C + c)*RR + bin0 + i]
    float* ob = out + (size_t)bp * NCH * RR + bin0;
    for (int jj = threadIdx.x; jj < 32 * NCH; jj += 256) {
        const int c = jj >> 5;       // channel
        const int i = jj & 31;       // bin within tile
        ob[(size_t)c * RR + i] = s[i][c];
    }
}

// ---------------------------------------------------------------------------
extern "C" void kernel_launch(void* const* d_in, const int* in_sizes, int n_in,
                              void* d_out, int out_size) {
    const float* xyz  = (const float*)d_in[0];  // (B, N, 3)
    const float* feat = (const float*)d_in[1];  // (B, C, N)
    float* out = (float*)d_out;                 // (B, 3, C, R, R)

    dim3 g1(NPTS / 32, BATCH), b1(32, 8);
    transpose_hist_kernel<<<g1, b1>>>(xyz, feat);

    scan_kernel<<<NBP, 1024>>>();

    scatter_idx_kernel<<<(TOTPTS + 255) / 256, 256>>>();

    gather_kernel<<<NBP * (RR / 32), 256>>>(out);
}